// round 4
// baseline (speedup 1.0000x reference)
#include <cuda_runtime.h>

#define NC 16
#define EPSV 1e-6f
#define B_DIM 2
#define D_DIM 8
#define H_DIM 96
#define W_DIM 96
#define DHW (D_DIM*H_DIM*W_DIM)     // 73728
#define HW  (H_DIM*W_DIM)           // 9216

#define TH 8
#define TW 32
#define NTHREADS (TH*TW)            // 256
#define HALO_H (TH+2)               // 10
#define HALO_W (TW+2)               // 34
#define NLOC   (3*HALO_H*HALO_W)    // 1020 halo locations (kt,yy,xx)
#define CSTRIDE 20                  // 16 ch + 4 pad (20 mod 8 == 4 -> conflict-free LDS.128)
#define SH_ELEMS (NLOC*CSTRIDE)     // 20400 floats
#define SMEM_FLOATS (SH_ELEMS + 256)
#define SMEM_BYTES (SMEM_FLOATS * 4)   // 82,624 B -> 2 CTAs/SM

// 9.4 MB scratch for head output, channel-contiguous: h[b][d][y][x][c]
__device__ float g_h[(size_t)B_DIM * DHW * NC];

// ---------------------------------------------------------------------------
// Kernel 1: h = relu(head_w @ x). Writes c-contiguous (4x STG.128 / location).
// ---------------------------------------------------------------------------
__global__ void head_kernel(const float* __restrict__ x,
                            const float* __restrict__ head_w) {
    __shared__ float sw[NC * NC];
    if (threadIdx.x < NC * NC) sw[threadIdx.x] = head_w[threadIdx.x];
    __syncthreads();

    int idx = blockIdx.x * blockDim.x + threadIdx.x;   // over b*D*H*W
    if (idx >= B_DIM * DHW) return;
    int b = idx / DHW;
    int s = idx - b * DHW;

    const float* xb = x + (size_t)b * NC * DHW + s;
    float xv[NC];
#pragma unroll
    for (int c = 0; c < NC; c++) xv[c] = xb[(size_t)c * DHW];

    float hv[NC];
#pragma unroll
    for (int o = 0; o < NC; o++) {
        float a = 0.f;
#pragma unroll
        for (int c = 0; c < NC; c++) a = fmaf(sw[o * NC + c], xv[c], a);
        hv[o] = fmaxf(a, 0.f);
    }
    float4* hb = (float4*)(g_h + (size_t)idx * NC);
#pragma unroll
    for (int q = 0; q < 4; q++)
        hb[q] = make_float4(hv[4*q], hv[4*q+1], hv[4*q+2], hv[4*q+3]);
}

// ---------------------------------------------------------------------------
// Kernel 2: per-location rank-degenerate NMF + tail.
// v[27] register-resident; 27-column bodies fully unrolled (immediate LDS
// offsets); step loop rolled.
// ---------------------------------------------------------------------------
__global__ void __launch_bounds__(NTHREADS, 2)
nmf_kernel(const float* __restrict__ tail_w, float* __restrict__ out) {
    extern __shared__ float smem[];
    float* sh = smem;                 // [kt][yy][xx][CSTRIDE] halo tile
    float* st = smem + SH_ELEMS;      // [256] tail weights

    const int tid = threadIdx.x;
    const int bz = blockIdx.z;
    const int b  = bz >> 3;
    const int d  = bz & 7;
    const int y0 = blockIdx.y * TH;
    const int x0 = blockIdx.x * TW;

    if (tid < NC * NC) st[tid] = tail_w[tid];

    // ---- stage halo tile: coalesced 64B/thread copies ----
    {
        const size_t hbase = (size_t)b * DHW * NC;
        for (int i = tid; i < NLOC; i += NTHREADS) {
            int xx = i % HALO_W;
            int r  = i / HALO_W;
            int yy = r % HALO_H;
            int kt = r / HALO_H;
            int gd = min(max(d + kt - 1, 0), D_DIM - 1);
            int gy = min(max(y0 + yy - 1, 0), H_DIM - 1);
            int gx = min(max(x0 + xx - 1, 0), W_DIM - 1);
            const float4* src = (const float4*)(g_h + hbase
                               + (size_t)((gd * H_DIM + gy) * W_DIM + gx) * NC);
            float4* dst = (float4*)(sh + i * CSTRIDE);
            dst[0] = src[0]; dst[1] = src[1]; dst[2] = src[2]; dst[3] = src[3];
        }
    }
    __syncthreads();

    const int ty = tid >> 5;
    const int tx = tid & 31;
    // Column k = (ki*3+kj)*3+kt at immediate offset from shp:
    //   ((kt*HALO_H + ki)*HALO_W + kj)*CSTRIDE
    const float* shp = sh + (ty * HALO_W + tx) * CSTRIDE;

#define KCOL(k) ((((k)%3)*HALO_H + ((k)/9))*HALO_W + (((k)/3)%3)) * CSTRIDE

    float u[NC];
#pragma unroll
    for (int c = 0; c < NC; c++) u[c] = 0.f;
    float v[27];

    // ---- init pass: u[c] = mean_k X, v[k] = mean_c X ----
#pragma unroll
    for (int k = 0; k < 27; k++) {
        const float4* p = (const float4*)(shp + KCOL(k));
        float s0 = 0.f, s1 = 0.f;
#pragma unroll
        for (int q = 0; q < 4; q++) {
            float4 xv = p[q];
            if (q & 1) s1 += (xv.x + xv.y) + (xv.z + xv.w);
            else       s0 += (xv.x + xv.y) + (xv.z + xv.w);
            u[4*q+0] += xv.x; u[4*q+1] += xv.y;
            u[4*q+2] += xv.z; u[4*q+3] += xv.w;
        }
        v[k] = (s0 + s1) * (1.f / 16.f);
    }
#pragma unroll
    for (int c = 0; c < NC; c++) u[c] *= (1.f / 27.f);

    // ---- 3 NMF steps ----
#pragma unroll 1
    for (int step = 0; step < 3; step++) {
        float uu = 0.f;
#pragma unroll
        for (int c = 0; c < NC; c++) uu = fmaf(u[c], u[c], uu);
        const float t_uu = 3.f * uu;

        float nu[NC];
#pragma unroll
        for (int c = 0; c < NC; c++) nu[c] = 0.f;
        float vv = 0.f;

#pragma unroll
        for (int k = 0; k < 27; k++) {
            const float4* p = (const float4*)(shp + KCOL(k));
            float4 a = p[0], bq = p[1], cq = p[2], dq = p[3];

            // 4 independent partial dot chains (ILP)
            float n0 = u[0]  * a.x;   n0 = fmaf(u[1],  a.y,  n0);
            n0 = fmaf(u[2],  a.z, n0); n0 = fmaf(u[3],  a.w,  n0);
            float n1 = u[4]  * bq.x;  n1 = fmaf(u[5],  bq.y, n1);
            n1 = fmaf(u[6],  bq.z, n1); n1 = fmaf(u[7],  bq.w, n1);
            float n2 = u[8]  * cq.x;  n2 = fmaf(u[9],  cq.y, n2);
            n2 = fmaf(u[10], cq.z, n2); n2 = fmaf(u[11], cq.w, n2);
            float n3 = u[12] * dq.x;  n3 = fmaf(u[13], dq.y, n3);
            n3 = fmaf(u[14], dq.z, n3); n3 = fmaf(u[15], dq.w, n3);
            float num = (n0 + n1) + (n2 + n3);

            float vk = v[k];
            float vn = vk * num * __frcp_rn(fmaf(t_uu, vk, EPSV));
            v[k] = vn;
            vv = fmaf(vn, vn, vv);

            nu[0]  = fmaf(a.x,  vn, nu[0]);  nu[1]  = fmaf(a.y,  vn, nu[1]);
            nu[2]  = fmaf(a.z,  vn, nu[2]);  nu[3]  = fmaf(a.w,  vn, nu[3]);
            nu[4]  = fmaf(bq.x, vn, nu[4]);  nu[5]  = fmaf(bq.y, vn, nu[5]);
            nu[6]  = fmaf(bq.z, vn, nu[6]);  nu[7]  = fmaf(bq.w, vn, nu[7]);
            nu[8]  = fmaf(cq.x, vn, nu[8]);  nu[9]  = fmaf(cq.y, vn, nu[9]);
            nu[10] = fmaf(cq.z, vn, nu[10]); nu[11] = fmaf(cq.w, vn, nu[11]);
            nu[12] = fmaf(dq.x, vn, nu[12]); nu[13] = fmaf(dq.y, vn, nu[13]);
            nu[14] = fmaf(dq.z, vn, nu[14]); nu[15] = fmaf(dq.w, vn, nu[15]);
        }
        const float t_vv = 3.f * vv;
#pragma unroll
        for (int c = 0; c < NC; c++)
            u[c] = u[c] * nu[c] * __frcp_rn(fmaf(t_vv, u[c], EPSV));
    }

    // ---- center tap + tail GEMV + relu ----
    const float v13 = v[13];
    float uvc[NC];
#pragma unroll
    for (int c = 0; c < NC; c++) uvc[c] = 3.f * u[c] * v13;

    const size_t outbase = (size_t)b * NC * DHW + (size_t)d * HW
                         + (size_t)(y0 + ty) * W_DIM + (x0 + tx);
#pragma unroll
    for (int i = 0; i < NC; i++) {
        float a = 0.f;
#pragma unroll
        for (int o = 0; o < NC; o++) a = fmaf(st[i * NC + o], uvc[o], a);
        out[outbase + (size_t)i * DHW] = fmaxf(a, 0.f);
    }
}

// ---------------------------------------------------------------------------
extern "C" void kernel_launch(void* const* d_in, const int* in_sizes, int n_in,
                              void* d_out, int out_size) {
    const float* x      = (const float*)d_in[0];
    const float* head_w = (const float*)d_in[1];
    const float* tail_w = (const float*)d_in[2];
    float* out = (float*)d_out;

    (void)in_sizes; (void)n_in; (void)out_size;

    cudaFuncSetAttribute(nmf_kernel,
                         cudaFuncAttributeMaxDynamicSharedMemorySize,
                         SMEM_BYTES);

    {   // head: one thread per spatial location
        int total = B_DIM * DHW;
        int threads = 256;
        int blocks = (total + threads - 1) / threads;
        head_kernel<<<blocks, threads>>>(x, head_w);
    }
    {
        dim3 grid(W_DIM / TW, H_DIM / TH, B_DIM * D_DIM);   // (3, 12, 16)
        nmf_kernel<<<grid, NTHREADS, SMEM_BYTES>>>(tail_w, out);
    }
}

// round 5
// speedup vs baseline: 4.1787x; 4.1787x over previous
#include <cuda_runtime.h>

#define NC 16
#define EPSV 1e-6f
#define B_DIM 2
#define D_DIM 8
#define H_DIM 96
#define W_DIM 96
#define DHW (D_DIM*H_DIM*W_DIM)     // 73728
#define HW  (H_DIM*W_DIM)           // 9216

// CTA tile: full depth x 4 y x 8 x
#define TD 8
#define TH 4
#define TW 8
#define NTHREADS (TD*TH*TW)         // 256
#define HALO_D (TD+2)               // 10
#define HALO_H (TH+2)               // 6
#define HALO_W (TW+2)               // 10
#define NLOC   (HALO_D*HALO_H*HALO_W) // 600 halo locations
#define CSTRIDE 20                  // 16 ch + 4 pad (20 mod 8 == 4 -> conflict-free LDS.128)
#define SH_ELEMS (NLOC*CSTRIDE)     // 12000 floats = 48000 B
#define SV_ELEMS (27*NTHREADS)      // 6912 floats  = 27648 B
#define TAILW_OFF (SH_ELEMS + SV_ELEMS)
#define SMEM_FLOATS (TAILW_OFF + 256)
#define SMEM_BYTES (SMEM_FLOATS * 4)   // 76,672 B -> 3 CTAs/SM

// 9.4 MB scratch for head output, channel-contiguous: h[b][d][y][x][c]
__device__ float g_h[(size_t)B_DIM * DHW * NC];

// ---------------------------------------------------------------------------
// Kernel 1: h = relu(head_w @ x). Writes c-contiguous (4x STG.128 / location).
// ---------------------------------------------------------------------------
__global__ void head_kernel(const float* __restrict__ x,
                            const float* __restrict__ head_w) {
    __shared__ float sw[NC * NC];
    if (threadIdx.x < NC * NC) sw[threadIdx.x] = head_w[threadIdx.x];
    __syncthreads();

    int idx = blockIdx.x * blockDim.x + threadIdx.x;   // over b*D*H*W
    if (idx >= B_DIM * DHW) return;
    int b = idx / DHW;
    int s = idx - b * DHW;

    const float* xb = x + (size_t)b * NC * DHW + s;
    float xv[NC];
#pragma unroll
    for (int c = 0; c < NC; c++) xv[c] = xb[(size_t)c * DHW];

    float hv[NC];
#pragma unroll
    for (int o = 0; o < NC; o++) {
        float a = 0.f;
#pragma unroll
        for (int c = 0; c < NC; c++) a = fmaf(sw[o * NC + c], xv[c], a);
        hv[o] = fmaxf(a, 0.f);
    }
    float4* hb = (float4*)(g_h + (size_t)idx * NC);
#pragma unroll
    for (int q = 0; q < 4; q++)
        hb[q] = make_float4(hv[4*q], hv[4*q+1], hv[4*q+2], hv[4*q+3]);
}

// ---------------------------------------------------------------------------
// Kernel 2: per-location rank-degenerate NMF + tail.
// Full-depth tile (d-halo amortized) -> 3 CTAs/SM. Rolled kk loop.
// ---------------------------------------------------------------------------
__global__ void __launch_bounds__(NTHREADS, 3)
nmf_kernel(const float* __restrict__ tail_w, float* __restrict__ out) {
    extern __shared__ float smem[];
    float* sh = smem;                 // [p][yy][xx][CSTRIDE] halo tile (p = d-plane)
    float* sv = smem + SH_ELEMS;      // [27][256] per-thread v
    float* st = smem + TAILW_OFF;     // [256] tail weights

    const int tid = threadIdx.x;
    const int b  = blockIdx.z;
    const int y0 = blockIdx.y * TH;
    const int x0 = blockIdx.x * TW;

    if (tid < NC * NC) st[tid] = tail_w[tid];

    // ---- stage halo tile: coalesced 64B/thread copies ----
    {
        const size_t hbase = (size_t)b * DHW * NC;
        for (int i = tid; i < NLOC; i += NTHREADS) {
            int xx = i % HALO_W;
            int r  = i / HALO_W;
            int yy = r % HALO_H;
            int p  = r / HALO_H;                       // 0..9 -> d-plane
            int gd = min(max(p - 1, 0), D_DIM - 1);
            int gy = min(max(y0 + yy - 1, 0), H_DIM - 1);
            int gx = min(max(x0 + xx - 1, 0), W_DIM - 1);
            const float4* src = (const float4*)(g_h + hbase
                               + (size_t)((gd * H_DIM + gy) * W_DIM + gx) * NC);
            float4* dst = (float4*)(sh + i * CSTRIDE);
            dst[0] = src[0]; dst[1] = src[1]; dst[2] = src[2]; dst[3] = src[3];
        }
    }
    __syncthreads();

    const int tx = tid & 7;
    const int ty = (tid >> 3) & 3;
    const int td = tid >> 5;
    // Column (ki,kj,kt): shp + ((kt*HALO_H + ki)*HALO_W + kj)*CSTRIDE
    const float* shp = sh + ((td * HALO_H + ty) * HALO_W + tx) * CSTRIDE;

    float u[NC];
#pragma unroll
    for (int c = 0; c < NC; c++) u[c] = 0.f;

    // ---- init pass: u[c] = mean_k X, v[k] = mean_c X ----
#pragma unroll 1
    for (int kk = 0; kk < 9; kk++) {          // kk = ki*3+kj
        const int ki = kk / 3, kj = kk - 3 * ki;
        const float* pbase = shp + (ki * HALO_W + kj) * CSTRIDE;
#pragma unroll
        for (int kt = 0; kt < 3; kt++) {
            const float4* p = (const float4*)(pbase + kt * (HALO_H * HALO_W * CSTRIDE));
            float s0 = 0.f, s1 = 0.f;
#pragma unroll
            for (int q = 0; q < 4; q++) {
                float4 xv = p[q];
                if (q & 1) s1 += (xv.x + xv.y) + (xv.z + xv.w);
                else       s0 += (xv.x + xv.y) + (xv.z + xv.w);
                u[4*q+0] += xv.x; u[4*q+1] += xv.y;
                u[4*q+2] += xv.z; u[4*q+3] += xv.w;
            }
            sv[(kk * 3 + kt) * NTHREADS + tid] = (s0 + s1) * (1.f / 16.f);
        }
    }
#pragma unroll
    for (int c = 0; c < NC; c++) u[c] *= (1.f / 27.f);

    // ---- 3 NMF steps ----
#pragma unroll 1
    for (int step = 0; step < 3; step++) {
        float uu = 0.f;
#pragma unroll
        for (int c = 0; c < NC; c++) uu = fmaf(u[c], u[c], uu);
        const float t_uu = 3.f * uu;

        float nu[NC];
#pragma unroll
        for (int c = 0; c < NC; c++) nu[c] = 0.f;
        float vv = 0.f;

#pragma unroll 1
        for (int kk = 0; kk < 9; kk++) {
            const int ki = kk / 3, kj = kk - 3 * ki;
            const float* pbase = shp + (ki * HALO_W + kj) * CSTRIDE;
#pragma unroll
            for (int kt = 0; kt < 3; kt++) {
                const float4* p = (const float4*)(pbase + kt * (HALO_H * HALO_W * CSTRIDE));

                float4 a = p[0], bq = p[1], cq = p[2], dq = p[3];

                // 2 independent dot chains
                float n0 = u[0] * a.x;      n0 = fmaf(u[1],  a.y,  n0);
                n0 = fmaf(u[2],  a.z, n0);  n0 = fmaf(u[3],  a.w,  n0);
                n0 = fmaf(u[4],  bq.x, n0); n0 = fmaf(u[5],  bq.y, n0);
                n0 = fmaf(u[6],  bq.z, n0); n0 = fmaf(u[7],  bq.w, n0);
                float n1 = u[8] * cq.x;     n1 = fmaf(u[9],  cq.y, n1);
                n1 = fmaf(u[10], cq.z, n1); n1 = fmaf(u[11], cq.w, n1);
                n1 = fmaf(u[12], dq.x, n1); n1 = fmaf(u[13], dq.y, n1);
                n1 = fmaf(u[14], dq.z, n1); n1 = fmaf(u[15], dq.w, n1);
                float num = n0 + n1;

                const int svi = (kk * 3 + kt) * NTHREADS + tid;
                float vk = sv[svi];
                float vn = vk * num * __frcp_rn(fmaf(t_uu, vk, EPSV));
                sv[svi] = vn;
                vv = fmaf(vn, vn, vv);

                nu[0]  = fmaf(a.x,  vn, nu[0]);  nu[1]  = fmaf(a.y,  vn, nu[1]);
                nu[2]  = fmaf(a.z,  vn, nu[2]);  nu[3]  = fmaf(a.w,  vn, nu[3]);
                nu[4]  = fmaf(bq.x, vn, nu[4]);  nu[5]  = fmaf(bq.y, vn, nu[5]);
                nu[6]  = fmaf(bq.z, vn, nu[6]);  nu[7]  = fmaf(bq.w, vn, nu[7]);
                nu[8]  = fmaf(cq.x, vn, nu[8]);  nu[9]  = fmaf(cq.y, vn, nu[9]);
                nu[10] = fmaf(cq.z, vn, nu[10]); nu[11] = fmaf(cq.w, vn, nu[11]);
                nu[12] = fmaf(dq.x, vn, nu[12]); nu[13] = fmaf(dq.y, vn, nu[13]);
                nu[14] = fmaf(dq.z, vn, nu[14]); nu[15] = fmaf(dq.w, vn, nu[15]);
            }
        }
        const float t_vv = 3.f * vv;
#pragma unroll
        for (int c = 0; c < NC; c++)
            u[c] = u[c] * nu[c] * __frcp_rn(fmaf(t_vv, u[c], EPSV));
    }

    // ---- center tap + tail GEMV + relu ----
    const float v13 = sv[13 * NTHREADS + tid];
    float uvc[NC];
#pragma unroll
    for (int c = 0; c < NC; c++) uvc[c] = 3.f * u[c] * v13;

    const size_t outbase = (size_t)b * NC * DHW + (size_t)td * HW
                         + (size_t)(y0 + ty) * W_DIM + (x0 + tx);
#pragma unroll
    for (int i = 0; i < NC; i++) {
        float a = 0.f;
#pragma unroll
        for (int o = 0; o < NC; o++) a = fmaf(st[i * NC + o], uvc[o], a);
        out[outbase + (size_t)i * DHW] = fmaxf(a, 0.f);
    }
}

// ---------------------------------------------------------------------------
extern "C" void kernel_launch(void* const* d_in, const int* in_sizes, int n_in,
                              void* d_out, int out_size) {
    const float* x      = (const float*)d_in[0];
    const float* head_w = (const float*)d_in[1];
    const float* tail_w = (const float*)d_in[2];
    float* out = (float*)d_out;

    (void)in_sizes; (void)n_in; (void)out_size;

    cudaFuncSetAttribute(nmf_kernel,
                         cudaFuncAttributeMaxDynamicSharedMemorySize,
                         SMEM_BYTES);
    cudaFuncSetAttribute(nmf_kernel,
                         cudaFuncAttributePreferredSharedMemoryCarveout,
                         100);

    {   // head: one thread per spatial location
        int total = B_DIM * DHW;
        int threads = 256;
        int blocks = (total + threads - 1) / threads;
        head_kernel<<<blocks, threads>>>(x, head_w);
    }
    {
        dim3 grid(W_DIM / TW, H_DIM / TH, B_DIM);   // (12, 24, 2) = 576 CTAs
        nmf_kernel<<<grid, NTHREADS, SMEM_BYTES>>>(tail_w, out);
    }
}

// round 7
// speedup vs baseline: 4.2136x; 1.0084x over previous
#include <cuda_runtime.h>

#define NC 16
#define EPSV 1e-6f
#define B_DIM 2
#define D_DIM 8
#define H_DIM 96
#define W_DIM 96
#define DHW (D_DIM*H_DIM*W_DIM)     // 73728
#define HW  (H_DIM*W_DIM)           // 9216

// CTA tile: full depth x 4 y x 8 x
#define TD 8
#define TH 4
#define TW 8
#define NTHREADS (TD*TH*TW)         // 256
#define HALO_D (TD+2)               // 10
#define HALO_H (TH+2)               // 6
#define HALO_W (TW+2)               // 10
#define NLOC   (HALO_D*HALO_H*HALO_W) // 600 halo locations
#define CSTRIDE 20                  // 16 ch + 4 pad (conflict-free LDS.128)
#define PLANE  (HALO_H*HALO_W*CSTRIDE)
#define SH_ELEMS (NLOC*CSTRIDE)     // 12000 floats = 48000 B
#define SV_ELEMS (27*NTHREADS)      // 6912 floats  = 27648 B
#define TAILW_OFF (SH_ELEMS + SV_ELEMS)
#define SMEM_FLOATS (TAILW_OFF + 256)
#define SMEM_BYTES (SMEM_FLOATS * 4)   // 76,672 B -> 3 CTAs/SM

typedef unsigned long long ull;

// ---- packed f32x2 helpers (Blackwell FFMA2 path, PTX-only) ----
__device__ __forceinline__ ull f2fma(ull a, ull b, ull c) {
    ull d; asm("fma.rn.f32x2 %0,%1,%2,%3;" : "=l"(d) : "l"(a), "l"(b), "l"(c)); return d;
}
__device__ __forceinline__ ull f2add(ull a, ull b) {
    ull d; asm("add.rn.f32x2 %0,%1,%2;" : "=l"(d) : "l"(a), "l"(b)); return d;
}
__device__ __forceinline__ ull f2mul(ull a, ull b) {
    ull d; asm("mul.rn.f32x2 %0,%1,%2;" : "=l"(d) : "l"(a), "l"(b)); return d;
}
__device__ __forceinline__ ull pack2(float lo, float hi) {
    ull d; asm("mov.b64 %0,{%1,%2};" : "=l"(d) : "f"(lo), "f"(hi)); return d;
}
__device__ __forceinline__ float2 unpack2(ull a) {
    float2 r; asm("mov.b64 {%0,%1},%2;" : "=f"(r.x), "=f"(r.y) : "l"(a)); return r;
}

// 9.4 MB scratch for head output, channel-contiguous: h[b][d][y][x][c]
__device__ float g_h[(size_t)B_DIM * DHW * NC];

// ---------------------------------------------------------------------------
// Kernel 1: h = relu(head_w @ x). Writes c-contiguous (4x STG.128 / location).
// ---------------------------------------------------------------------------
__global__ void head_kernel(const float* __restrict__ x,
                            const float* __restrict__ head_w) {
    __shared__ float sw[NC * NC];
    if (threadIdx.x < NC * NC) sw[threadIdx.x] = head_w[threadIdx.x];
    __syncthreads();

    int idx = blockIdx.x * blockDim.x + threadIdx.x;   // over b*D*H*W
    if (idx >= B_DIM * DHW) return;
    int b = idx / DHW;
    int s = idx - b * DHW;

    const float* xb = x + (size_t)b * NC * DHW + s;
    float xv[NC];
#pragma unroll
    for (int c = 0; c < NC; c++) xv[c] = xb[(size_t)c * DHW];

    float hv[NC];
#pragma unroll
    for (int o = 0; o < NC; o++) {
        float a = 0.f;
#pragma unroll
        for (int c = 0; c < NC; c++) a = fmaf(sw[o * NC + c], xv[c], a);
        hv[o] = fmaxf(a, 0.f);
    }
    float4* hb = (float4*)(g_h + (size_t)idx * NC);
#pragma unroll
    for (int q = 0; q < 4; q++)
        hb[q] = make_float4(hv[4*q], hv[4*q+1], hv[4*q+2], hv[4*q+3]);
}

// ---------------------------------------------------------------------------
// Kernel 2: per-location rank-degenerate NMF + tail, packed f32x2 math.
// ---------------------------------------------------------------------------
__global__ void __launch_bounds__(NTHREADS, 3)
nmf_kernel(const float* __restrict__ tail_w, float* __restrict__ out) {
    extern __shared__ float smem[];
    float* sh = smem;                 // [p][yy][xx][CSTRIDE] halo tile
    float* sv = smem + SH_ELEMS;      // [27][256] per-thread v
    float* st = smem + TAILW_OFF;     // [256] tail weights

    const int tid = threadIdx.x;
    const int b  = blockIdx.z;
    const int y0 = blockIdx.y * TH;
    const int x0 = blockIdx.x * TW;

    if (tid < NC * NC) st[tid] = tail_w[tid];

    // ---- stage halo tile: coalesced 64B/thread copies ----
    {
        const size_t hbase = (size_t)b * DHW * NC;
        for (int i = tid; i < NLOC; i += NTHREADS) {
            int xx = i % HALO_W;
            int r  = i / HALO_W;
            int yy = r % HALO_H;
            int p  = r / HALO_H;                       // d-plane 0..9
            int gd = min(max(p - 1, 0), D_DIM - 1);
            int gy = min(max(y0 + yy - 1, 0), H_DIM - 1);
            int gx = min(max(x0 + xx - 1, 0), W_DIM - 1);
            const float4* src = (const float4*)(g_h + hbase
                               + (size_t)((gd * H_DIM + gy) * W_DIM + gx) * NC);
            float4* dst = (float4*)(sh + i * CSTRIDE);
            dst[0] = src[0]; dst[1] = src[1]; dst[2] = src[2]; dst[3] = src[3];
        }
    }
    __syncthreads();

    const int tx = tid & 7;
    const int ty = (tid >> 3) & 3;
    const int td = tid >> 5;
    const float* shp = sh + ((td * HALO_H + ty) * HALO_W + tx) * CSTRIDE;

    ull up[8];
#pragma unroll
    for (int j = 0; j < 8; j++) up[j] = 0ull;   // two packed 0.0f

    // ---- init pass: u[c] = mean_k X, v[k] = mean_c X ----
#pragma unroll 1
    for (int kk = 0; kk < 9; kk++) {            // kk = ki*3+kj
        const int ki = kk / 3, kj = kk - 3 * ki;
        const float* pbase = shp + (ki * HALO_W + kj) * CSTRIDE;
        const int svb = kk * 3 * NTHREADS + tid;
#pragma unroll
        for (int kt = 0; kt < 3; kt++) {
            const ulonglong2* p = (const ulonglong2*)(pbase + kt * PLANE);
            ulonglong2 q0 = p[0], q1 = p[1], q2 = p[2], q3 = p[3];
            ull xp[8] = {q0.x, q0.y, q1.x, q1.y, q2.x, q2.y, q3.x, q3.y};
#pragma unroll
            for (int j = 0; j < 8; j++) up[j] = f2add(up[j], xp[j]);
            ull t0 = f2add(xp[0], xp[1]);
            ull t1 = f2add(xp[2], xp[3]);
            ull t2 = f2add(xp[4], xp[5]);
            ull t3 = f2add(xp[6], xp[7]);
            t0 = f2add(t0, t1); t2 = f2add(t2, t3);
            float2 s2 = unpack2(f2add(t0, t2));
            sv[svb + kt * NTHREADS] = (s2.x + s2.y) * (1.f / 16.f);
        }
    }
    {
        const ull c27 = pack2(1.f / 27.f, 1.f / 27.f);
#pragma unroll
        for (int j = 0; j < 8; j++) up[j] = f2mul(up[j], c27);
    }

    // ---- 3 NMF steps ----
#pragma unroll 1
    for (int step = 0; step < 3; step++) {
        ull uup = 0ull;
#pragma unroll
        for (int j = 0; j < 8; j++) uup = f2fma(up[j], up[j], uup);
        float2 uu2 = unpack2(uup);
        const float t_uu = 3.f * (uu2.x + uu2.y);

        ull nup[8];
#pragma unroll
        for (int j = 0; j < 8; j++) nup[j] = 0ull;
        float vv = 0.f;

#pragma unroll 1
        for (int kk = 0; kk < 9; kk++) {
            const int ki = kk / 3, kj = kk - 3 * ki;
            const float* pbase = shp + (ki * HALO_W + kj) * CSTRIDE;
            const int svb = kk * 3 * NTHREADS + tid;
#pragma unroll
            for (int kt = 0; kt < 3; kt++) {
                const ulonglong2* p = (const ulonglong2*)(pbase + kt * PLANE);
                ulonglong2 q0 = p[0], q1 = p[1], q2 = p[2], q3 = p[3];
                ull xp[8] = {q0.x, q0.y, q1.x, q1.y, q2.x, q2.y, q3.x, q3.y};

                // num = u . X[:,k]  (2 packed chains)
                ull np0 = f2mul(up[0], xp[0]);
                np0 = f2fma(up[2], xp[2], np0);
                np0 = f2fma(up[4], xp[4], np0);
                np0 = f2fma(up[6], xp[6], np0);
                ull np1 = f2mul(up[1], xp[1]);
                np1 = f2fma(up[3], xp[3], np1);
                np1 = f2fma(up[5], xp[5], np1);
                np1 = f2fma(up[7], xp[7], np1);
                float2 ns = unpack2(f2add(np0, np1));
                float num = ns.x + ns.y;

                const int svi = svb + kt * NTHREADS;
                float vk = sv[svi];
                float vn = vk * num * __frcp_rn(fmaf(t_uu, vk, EPSV));
                sv[svi] = vn;
                vv = fmaf(vn, vn, vv);
                ull vn2 = pack2(vn, vn);
#pragma unroll
                for (int j = 0; j < 8; j++) nup[j] = f2fma(xp[j], vn2, nup[j]);
            }
        }
        const float t_vv = 3.f * vv;
#pragma unroll
        for (int j = 0; j < 8; j++) {
            float2 a  = unpack2(up[j]);
            float2 nb = unpack2(nup[j]);
            float c0 = a.x * nb.x * __frcp_rn(fmaf(t_vv, a.x, EPSV));
            float c1 = a.y * nb.y * __frcp_rn(fmaf(t_vv, a.y, EPSV));
            up[j] = pack2(c0, c1);
        }
    }

    // ---- center tap + tail GEMV + relu (packed) ----
    const float v13 = sv[13 * NTHREADS + tid];
    const ull v13p = pack2(3.f * v13, 3.f * v13);
    ull uvcp[8];
#pragma unroll
    for (int j = 0; j < 8; j++) uvcp[j] = f2mul(up[j], v13p);

    const size_t outbase = (size_t)b * NC * DHW + (size_t)td * HW
                         + (size_t)(y0 + ty) * W_DIM + (x0 + tx);
#pragma unroll
    for (int i = 0; i < NC; i++) {
        const ulonglong2* wr = (const ulonglong2*)(st + i * NC);
        ulonglong2 w0 = wr[0], w1 = wr[1], w2 = wr[2], w3 = wr[3];
        ull acc0 = f2mul(w0.x, uvcp[0]);
        acc0 = f2fma(w1.x, uvcp[2], acc0);
        acc0 = f2fma(w2.x, uvcp[4], acc0);
        acc0 = f2fma(w3.x, uvcp[6], acc0);
        ull acc1 = f2mul(w0.y, uvcp[1]);
        acc1 = f2fma(w1.y, uvcp[3], acc1);
        acc1 = f2fma(w2.y, uvcp[5], acc1);
        acc1 = f2fma(w3.y, uvcp[7], acc1);
        float2 r2 = unpack2(f2add(acc0, acc1));
        out[outbase + (size_t)i * DHW] = fmaxf(r2.x + r2.y, 0.f);
    }
}

// ---------------------------------------------------------------------------
extern "C" void kernel_launch(void* const* d_in, const int* in_sizes, int n_in,
                              void* d_out, int out_size) {
    const float* x      = (const float*)d_in[0];
    const float* head_w = (const float*)d_in[1];
    const float* tail_w = (const float*)d_in[2];
    float* out = (float*)d_out;

    (void)in_sizes; (void)n_in; (void)out_size;

    cudaFuncSetAttribute(nmf_kernel,
                         cudaFuncAttributeMaxDynamicSharedMemorySize,
                         SMEM_BYTES);
    cudaFuncSetAttribute(nmf_kernel,
                         cudaFuncAttributePreferredSharedMemoryCarveout,
                         100);

    {   // head: one thread per spatial location
        int total = B_DIM * DHW;
        int threads = 256;
        int blocks = (total + threads - 1) / threads;
        head_kernel<<<blocks, threads>>>(x, head_w);
    }
    {
        dim3 grid(W_DIM / TW, H_DIM / TH, B_DIM);   // (12, 24, 2) = 576 CTAs
        nmf_kernel<<<grid, NTHREADS, SMEM_BYTES>>>(tail_w, out);
    }
}